// round 8
// baseline (speedup 1.0000x reference)
#include <cuda_runtime.h>

// BKT_RNN: B=8192, T=2048, H=4, X=1.
// R8: 8 lanes per row (maximum sigmoid-level parallelism): lanes 0-3 compute
// the 4 p-sigmoids, lanes 4-7 the 4 h-sigmoids, one sigmoid per lane per
// step through a single unified code path. 4 rows/warp -> 2048 one-warp
// blocks (2x R7's occupancy; profile showed issue=35%, occ=10.7%,
// latency-bound). Closed-form BKT latent (R4). Fused last-block loss.

#define TT 2048
#define BB 8192
#define NBLK (BB / 4)   // 2048 one-warp blocks

typedef unsigned long long u64;

__device__ float    g_part[NBLK];
__device__ unsigned g_done = 0;

__device__ __forceinline__ float ex2f(float v) {
    float r; asm("ex2.approx.f32 %0, %1;" : "=f"(r) : "f"(v)); return r;
}
__device__ __forceinline__ float rcpf(float v) {
    float r; asm("rcp.approx.f32 %0, %1;" : "=f"(r) : "f"(v)); return r;
}
__device__ __forceinline__ float lg2f(float v) {
    float r; asm("lg2.approx.f32 %0, %1;" : "=f"(r) : "f"(v)); return r;
}
__device__ __forceinline__ u64 pack2(float lo, float hi) {
    u64 r; asm("mov.b64 %0, {%1, %2};" : "=l"(r) : "f"(lo), "f"(hi)); return r;
}
__device__ __forceinline__ void unpack2(u64 v, float& lo, float& hi) {
    asm("mov.b64 {%0, %1}, %2;" : "=f"(lo), "=f"(hi) : "l"(v));
}

__global__ void __launch_bounds__(32) k_bkt(
    const float* __restrict__ x,   const float* __restrict__ y,
    const float* __restrict__ Wxh, const float* __restrict__ Whh,
    const float* __restrict__ bh,  const float* __restrict__ Wy,
    const float* __restrict__ by,  const float* __restrict__ prior,
    float* __restrict__ corrects,  float* __restrict__ latents,
    float* __restrict__ loss)
{
    const unsigned FULL = 0xffffffffu;
    const int lane = threadIdx.x;
    const int i    = lane & 7;                  // role within 8-lane group
    const int j    = i & 3;                     // unit index
    const bool is_h = (i & 4) != 0;             // lanes 4-7: h-sigmoids
    const int b    = blockIdx.x * 4 + (lane >> 3);

    // Unified per-lane weights, pre-scaled by -log2(e)
    // (sigmoid(z) = rcp(1 + ex2(z_scaled))).
    //   p-lane j: bias=by[j],  xcoef=0,      Wm = Wy[:,j]
    //   h-lane j: bias=bh[j],  xcoef=Wxh[j], Wm = Whh[:,j]
    // Rows permuted to the gather order [j, j^1, j^2, j^3].
    const float NL2E = -1.4426950408889634f;
    const float* Wsrc = is_h ? Whh : Wy;
    float Wc[4];
    #pragma unroll
    for (int m = 0; m < 4; m++)
        Wc[m] = NL2E * __ldg(Wsrc + (j ^ m) * 4 + j);
    const float bias  = NL2E * __ldg((is_h ? bh : by) + j);
    const float xcoef = is_h ? (NL2E * __ldg(Wxh + j)) : 0.f;

    float hj   = 0.f;              // meaningful on h-lanes
    float lat  = __ldg(prior);     // authoritative on lane i==0 of each group
    float lsum = 0.f;
    const bool odd     = (i & 1) != 0;
    const bool is_corr = ((i & 6) == 2);        // lanes 2,3: correct series
    const bool is_out  = (i & 4) == 0;          // lanes 0-3 store outputs

    const float4* xp = (const float4*)(x + (size_t)b * TT);
    const float4* yp = (const float4*)(y + (size_t)b * TT);
    // lanes 0/1 -> latents, lanes 2/3 -> corrects.
    float4* op = (float4*)(((i & 2) ? corrects : latents) + (size_t)b * TT);

    // Prime pipeline (chunk 0 = 8 timesteps). 8 lanes share addresses ->
    // broadcast; 8 distinct 16B segments per warp per array.
    float4 xa = __ldcs(xp + 0), xb = __ldcs(xp + 1);
    float4 ya = __ldcs(yp + 0), yb = __ldcs(yp + 1);

    const int NCHUNK = TT / 8;
    for (int c = 0; c < NCHUNK; ++c) {
        float xv[8] = {xa.x, xa.y, xa.z, xa.w, xb.x, xb.y, xb.z, xb.w};
        float yv[8] = {ya.x, ya.y, ya.z, ya.w, yb.x, yb.y, yb.z, yb.w};

        if (c + 1 < NCHUNK) {   // prefetch next chunk under compute
            xa = __ldcs(xp + 2 * c + 2); xb = __ldcs(xp + 2 * c + 3);
            ya = __ldcs(yp + 2 * c + 2); yb = __ldcs(yp + 2 * c + 3);
        }

        float rb[8];
        float prod = 1.f;

        #pragma unroll
        for (int k = 0; k < 8; k++) {
            // ---- h all-gather (4 SASS shuffles) ----
            // 1) bring h from h-lanes down to p-lanes (xor 4):
            const float hx = __shfl_xor_sync(FULL, hj, 4);
            const float h0 = is_h ? hj : hx;     // h_{j} on every lane
            // 2) 4-lane gather within each half (xor1 + u64 xor2):
            const float h1 = __shfl_xor_sync(FULL, h0, 1);   // h_{j^1}
            const u64   pk = pack2(h0, h1);
            const u64   rv = __shfl_xor_sync(FULL, pk, 2);
            float h2, h3; unpack2(rv, h2, h3);   // h_{j^2}, h_{j^3}

            // ---- one dot + one sigmoid per lane (unified) ----
            const float z = fmaf(h1, Wc[1],
                                 fmaf(h0, Wc[0], fmaf(xv[k], xcoef, bias))) +
                            fmaf(h2, Wc[2], h3 * Wc[3]);
            const float sg = rcpf(1.f + ex2f(z));
            if (is_h) hj = sg;        // h-lanes: new hidden state
            // p-lanes: sg = p_j

            // ---- latent / correct: unified FMA form ----
            // lanes 0,1: (l,f) -> res = l + lat*(1-l-f) = lat'
            // lanes 2,3: (g,s) -> res = g + lat*(1-g-s) = correct
            const float po   = __shfl_xor_sync(FULL, sg, 1);
            const float coef = 1.f - sg - po;
            const float base = odd ? po : sg;
            const float latc = __shfl_sync(FULL, lat, 0, 8); // lane 0's lat
            const float res  = fmaf(latc, coef, base);
            lat = res;                 // only lane 0's copy is read
            rb[k] = res;

            // ---- loss (lanes 2,3; y in {0,1} -> one factor) ----
            const float cc = fminf(fmaxf(res, 1e-7f), 1.0f - 1e-7f);
            prod *= (yv[k] != 0.f) ? cc : (1.f - cc);
            if ((k & 3) == 3) {
                lsum += is_corr ? lg2f(prod) : 0.f;
                prod = 1.f;
            }
        }

        // lanes 0-3 store: even lane -> elems 0..3, odd lane -> 4..7.
        if (is_out) {
            const float4 v = odd ? make_float4(rb[4], rb[5], rb[6], rb[7])
                                 : make_float4(rb[0], rb[1], rb[2], rb[3]);
            __stcs(op + 2 * c + (odd ? 1 : 0), v);
        }
    }

    // Warp reduce (each row counted 2x: lanes 2 and 3) -> per-block slot.
    #pragma unroll
    for (int o = 16; o > 0; o >>= 1)
        lsum += __shfl_xor_sync(FULL, lsum, o);
    if (lane == 0)
        g_part[blockIdx.x] = lsum;
    __threadfence();

    // Last-block-done reduction (fused finalize).
    unsigned ticket = 0;
    if (lane == 0) ticket = atomicAdd(&g_done, 1u);
    ticket = __shfl_sync(FULL, ticket, 0);
    if (ticket == NBLK - 1) {
        double acc = 0.0;
        for (int t = lane; t < NBLK; t += 32)
            acc += (double)g_part[t];
        #pragma unroll
        for (int o = 16; o > 0; o >>= 1)
            acc += __shfl_xor_sync(FULL, acc, o);
        if (lane == 0) {
            loss[0] = (float)(-0.6931471805599453 * acc /
                              (2.0 * (double)BB * (double)TT));
            g_done = 0;   // re-arm for the next graph replay
        }
    }
}

extern "C" void kernel_launch(void* const* d_in, const int* in_sizes, int n_in,
                              void* d_out, int out_size) {
    const float* x     = (const float*)d_in[0];
    const float* y     = (const float*)d_in[1];
    const float* Wxh   = (const float*)d_in[2];
    const float* Whh   = (const float*)d_in[3];
    const float* bh    = (const float*)d_in[4];
    const float* Wy    = (const float*)d_in[5];
    const float* by    = (const float*)d_in[6];
    const float* prior = (const float*)d_in[7];

    float* corrects = (float*)d_out;
    float* latents  = (float*)d_out + (size_t)BB * TT;
    float* loss     = (float*)d_out + 2 * (size_t)BB * TT;

    k_bkt<<<NBLK, 32>>>(x, y, Wxh, Whh, bh, Wy, by, prior,
                        corrects, latents, loss);
}